// round 12
// baseline (speedup 1.0000x reference)
#include <cuda_runtime.h>
#include <cstdint>

// ---------------- scratch ----------------
__device__ float g_Qp[256 * 9216];   // Q'[f][p]
__device__ float g_Qt[9216 * 256];   // Q'[p][f]
__device__ float g_Xt[9216 * 256];   // X [p][f]
__device__ float g_Vt[64 * 9216];    // V [c][p]
__device__ float g_cA[8 * 256], g_cB[256], g_cC[256];

// ---------------- helpers ----------------
__device__ __forceinline__ float tf32hi(float x) {
    uint32_t u;
    asm("cvt.rna.tf32.f32 %0, %1;" : "=r"(u) : "f"(x));
    return __uint_as_float(u);
}
__device__ __forceinline__ void split(float v, uint32_t& hi, uint32_t& lo) {
    float h = tf32hi(v);
    hi = __float_as_uint(h);
    lo = __float_as_uint(v - h);
}
// D(16x8,f32) += A(16x8,tf32,row) * B(8x8,tf32,col)
__device__ __forceinline__ void mma8(float* d, uint32_t a0, uint32_t a1,
                                     uint32_t a2, uint32_t a3,
                                     uint32_t b0, uint32_t b1) {
    asm volatile(
        "mma.sync.aligned.m16n8k8.row.col.f32.tf32.tf32.f32 "
        "{%0,%1,%2,%3}, {%4,%5,%6,%7}, {%8,%9}, {%0,%1,%2,%3};"
        : "+f"(d[0]), "+f"(d[1]), "+f"(d[2]), "+f"(d[3])
        : "r"(a0), "r"(a1), "r"(a2), "r"(a3), "r"(b0), "r"(b1));
}

// ---------------- kernel 1: per-feature coefficients ----------------
__global__ void coef_kernel(const float* __restrict__ WQ_task, const float* __restrict__ BQ_task,
                            const float* __restrict__ WK_task, const float* __restrict__ WQ_tm1,
                            const float* __restrict__ WQ_x, const float* __restrict__ BQ,
                            const float* __restrict__ WK_x) {
    int f = threadIdx.x;
    float kA = WK_task[f] * WK_x[f];
    float sW = 0.f, sB = 0.f;
#pragma unroll
    for (int h = 0; h < 8; h++) {
        float wq = WQ_task[h * 256 + f];
        sW += wq;
        sB += wq * BQ[h * 256 + f] + BQ_task[h * 256 + f];
        g_cA[h * 256 + f] = kA * wq * WQ_tm1[h * 256 + f];
    }
    g_cB[f] = kA * WQ_x[f] * sW;
    g_cC[f] = kA * sB;
}

// ---------------- kernel 2: Q' [f][p] ----------------
__global__ void qprep_kernel(const float* __restrict__ X, const float* __restrict__ prevQ) {
    int f = blockIdx.y;
    int p = blockIdx.x * 256 + threadIdx.x;
    float q = fmaf(g_cB[f], X[f * 9216 + p], g_cC[f]);
#pragma unroll
    for (int h = 0; h < 8; h++)
        q = fmaf(g_cA[h * 256 + f], prevQ[(h * 256 + f) * 9216 + p], q);
    g_Qp[f * 9216 + p] = q;
}

// ---------------- kernel 3: transpose [f][p] -> [p][f] ----------------
__global__ void trans_kernel(const float* __restrict__ src, float* __restrict__ dst) {
    __shared__ float t[32][33];
    int bx = blockIdx.x, by = blockIdx.y;
    int tx = threadIdx.x, ty = threadIdx.y;
#pragma unroll
    for (int j = 0; j < 4; j++)
        t[ty + j * 8][tx] = src[(by * 32 + ty + j * 8) * 9216 + bx * 32 + tx];
    __syncthreads();
#pragma unroll
    for (int j = 0; j < 4; j++)
        dst[(bx * 32 + ty + j * 8) * 256 + by * 32 + tx] = t[tx][ty + j * 8];
}

// ---------------- kernel 4: 3x3 conv (F=256->C=64) + affine -> g_Vt[c][p] ----------------
__global__ void __launch_bounds__(256) conv_kernel(const float* __restrict__ X,
                                                   const float* __restrict__ Wc,
                                                   const float* __restrict__ Bc,
                                                   const float* __restrict__ WV,
                                                   const float* __restrict__ BV) {
    __shared__ float sx[4 * 294];
    __shared__ float sw[4 * 288];
    const int tid = threadIdx.x;
    const int w = blockIdx.x;
    const int cbase = blockIdx.y * 32;
    const int cl = tid >> 3;
    const int c = cbase + cl;
    const int h0 = (tid & 7) * 12;
    float acc[12];
#pragma unroll
    for (int i = 0; i < 12; i++) acc[i] = 0.f;
    for (int fc = 0; fc < 256; fc += 4) {
        __syncthreads();
        for (int i = tid; i < 4 * 294; i += 256) {
            int ff = i / 294, r = i % 294;
            int dw = r / 98, hh = r % 98;
            int ww = w + dw - 1;
            float v = 0.f;
            if (ww >= 0 && ww < 96 && hh >= 1 && hh <= 96)
                v = X[(fc + ff) * 9216 + ww * 96 + hh - 1];
            sx[i] = v;
        }
        for (int i = tid; i < 4 * 288; i += 256) {
            int ff = i / 288, r = i % 288;
            sw[i] = Wc[((cbase + r / 9) * 256 + fc + ff) * 9 + r % 9];
        }
        __syncthreads();
#pragma unroll
        for (int ff = 0; ff < 4; ff++) {
            float wv[9];
#pragma unroll
            for (int s = 0; s < 9; s++) wv[s] = sw[ff * 288 + cl * 9 + s];
#pragma unroll
            for (int dw = 0; dw < 3; dw++) {
                float xr[14];
#pragma unroll
                for (int j = 0; j < 14; j++) xr[j] = sx[ff * 294 + dw * 98 + h0 + j];
#pragma unroll
                for (int hi = 0; hi < 12; hi++)
#pragma unroll
                    for (int dh = 0; dh < 3; dh++)
                        acc[hi] = fmaf(xr[hi + dh], wv[dw * 3 + dh], acc[hi]);
            }
        }
    }
    float wv_ = WV[c], bv_ = BV[c], bc_ = Bc[c];
#pragma unroll
    for (int hi = 0; hi < 12; hi++)
        g_Vt[c * 9216 + w * 96 + h0 + hi] = fmaf(wv_, acc[hi] + bc_, bv_);
}

// ---------------- kernel 5: flash attention via mma.sync tf32 ----------------
// grid 144: CTA = 64 queries x all 9216 keys (72 tiles of 128).
// 512 thr = 16 warps = 4 q-quarters(16q) x 4 k-cols(32k). 3-pass tf32 split.
// smem floats: sQ 64x260 | sX 2x(128x36) | sP 64x132 | sV 64x132 | redM/redS 4x64
static const int SQ = 0, SX0 = 16640, SX1 = 21248, SP = 25856, SV = 34304;
static const int RM = 42752, RS = 43008;
static const int ATTN_SMEM = 43264 * 4;

__device__ __forceinline__ void ldgX(int cc, int tid, float4* rv) {
    int q0 = (cc >> 3) << 7, fb = (cc & 7) << 5;
#pragma unroll
    for (int j = 0; j < 2; j++) {
        int idx = tid + j * 512;
        int key = idx >> 3, f4 = idx & 7;
        rv[j] = *(const float4*)(g_Xt + (q0 + key) * 256 + fb + f4 * 4);
    }
}
__device__ __forceinline__ void stsX(float* dst, int tid, const float4* rv) {
#pragma unroll
    for (int j = 0; j < 2; j++) {
        int idx = tid + j * 512;
        int key = idx >> 3, f4 = idx & 7;
        *(float4*)(dst + key * 36 + f4 * 4) = rv[j];
    }
}

__global__ void __launch_bounds__(512, 1)
attn_kernel(float* __restrict__ out) {
    extern __shared__ float sm[];
    const int tid = threadIdx.x;
    const int w = tid >> 5, l = tid & 31;
    const int g = l >> 2, t = l & 3;
    const int qq = w >> 2;     // query quarter: rows qq*16..+15
    const int kc = w & 3;      // key column: keys kc*32..+31 / channels kc*16..+15
    const int p0 = blockIdx.x * 64;

    float* sQ = sm + SQ;
    float* sXb[2] = { sm + SX0, sm + SX1 };
    float* sP = sm + SP;
    float* sV = sm + SV;
    float* redM = sm + RM;
    float* redS = sm + RS;

    // stage Q tile [64][260]
#pragma unroll
    for (int i = 0; i < 8; i++) {
        int idx = tid + i * 512;
        int q = idx >> 6, f4 = idx & 63;
        *(float4*)(sQ + q * 260 + f4 * 4) = *(const float4*)(g_Qt + (p0 + q) * 256 + f4 * 4);
    }

    float4 rv[2];
    ldgX(0, tid, rv);
    __syncthreads();

    float o[2][4];
#pragma unroll
    for (int b = 0; b < 2; b++)
#pragma unroll
        for (int j = 0; j < 4; j++) o[b][j] = 0.f;
    float m_[2] = { -1e30f, -1e30f }, l_[2] = { 0.f, 0.f };

    for (int kt = 0; kt < 72; kt++) {
        const int q0 = kt * 128;
        float s[4][4];
#pragma unroll
        for (int n = 0; n < 4; n++)
#pragma unroll
            for (int j = 0; j < 4; j++) s[n][j] = 0.f;

        // ---- QK: 8 chunks of 32 features ----
        for (int ch = 0; ch < 8; ch++) {
            const int cc = kt * 8 + ch;
            float* sX = sXb[cc & 1];
            stsX(sX, tid, rv);
            if (cc + 1 < 576) ldgX(cc + 1, tid, rv);
            __syncthreads();

#pragma unroll
            for (int ks = 0; ks < 4; ks++) {
                const int fo = ch * 32 + ks * 8;
                uint32_t ah[4], al[4], bh[4][2], bl[4][2];
                const float* qr = sQ + (qq * 16) * 260 + fo;
                split(qr[g * 260 + t],           ah[0], al[0]);
                split(qr[(g + 8) * 260 + t],     ah[1], al[1]);
                split(qr[g * 260 + t + 4],       ah[2], al[2]);
                split(qr[(g + 8) * 260 + t + 4], ah[3], al[3]);
#pragma unroll
                for (int nt = 0; nt < 4; nt++) {
                    const float* xr = sX + (kc * 32 + nt * 8 + g) * 36 + ks * 8;
                    split(xr[t],     bh[nt][0], bl[nt][0]);
                    split(xr[t + 4], bh[nt][1], bl[nt][1]);
                }
#pragma unroll
                for (int nt = 0; nt < 4; nt++)
                    mma8(s[nt], ah[0], ah[1], ah[2], ah[3], bh[nt][0], bh[nt][1]);
#pragma unroll
                for (int nt = 0; nt < 4; nt++)
                    mma8(s[nt], al[0], al[1], al[2], al[3], bh[nt][0], bh[nt][1]);
#pragma unroll
                for (int nt = 0; nt < 4; nt++)
                    mma8(s[nt], ah[0], ah[1], ah[2], ah[3], bl[nt][0], bl[nt][1]);
            }
            __syncthreads();
        }

        // ---- softmax part 1: row maxes (rows qq*16 + h2*8 + g) ----
        float rm[2];
#pragma unroll
        for (int h2 = 0; h2 < 2; h2++) {
            float v = s[0][2 * h2];
#pragma unroll
            for (int nt = 0; nt < 4; nt++) {
                v = fmaxf(v, s[nt][2 * h2]);
                v = fmaxf(v, s[nt][2 * h2 + 1]);
            }
            v = fmaxf(v, __shfl_xor_sync(0xffffffffu, v, 1));
            v = fmaxf(v, __shfl_xor_sync(0xffffffffu, v, 2));
            rm[h2] = v;
        }
        if (t == 0) {
#pragma unroll
            for (int h2 = 0; h2 < 2; h2++)
                redM[kc * 64 + qq * 16 + h2 * 8 + g] = rm[h2];
        }
        __syncthreads();

        // ---- stage V tile [64c][128k] (LDG early, hides under exp) ----
#pragma unroll
        for (int j = 0; j < 4; j++) {
            int idx = tid + j * 512;
            int c = idx >> 5, k4 = idx & 31;
            float4 v = *(const float4*)(g_Vt + c * 9216 + q0 + k4 * 4);
            *(float4*)(sV + c * 132 + k4 * 4) = v;
        }

        // ---- softmax part 2: exp, sums, P to smem ----
        float mn[2], sc[2];
#pragma unroll
        for (int h2 = 0; h2 < 2; h2++) {
            int row = qq * 16 + h2 * 8 + g;
            float mx = fmaxf(fmaxf(redM[row], redM[64 + row]),
                             fmaxf(redM[128 + row], redM[192 + row]));
            mn[h2] = fmaxf(m_[h2], mx);
            sc[h2] = __expf(m_[h2] - mn[h2]);
            m_[h2] = mn[h2];
            float rs = 0.f;
#pragma unroll
            for (int nt = 0; nt < 4; nt++) {
                float e0 = __expf(s[nt][2 * h2] - mn[h2]);
                float e1 = __expf(s[nt][2 * h2 + 1] - mn[h2]);
                s[nt][2 * h2] = e0;
                s[nt][2 * h2 + 1] = e1;
                rs += e0 + e1;
            }
            rs += __shfl_xor_sync(0xffffffffu, rs, 1);
            rs += __shfl_xor_sync(0xffffffffu, rs, 2);
            if (t == 0) redS[kc * 64 + row] = rs;
        }
        // write P: [q][k]
#pragma unroll
        for (int h2 = 0; h2 < 2; h2++) {
            int row = qq * 16 + h2 * 8 + g;
#pragma unroll
            for (int nt = 0; nt < 4; nt++) {
                float2 pv = make_float2(s[nt][2 * h2], s[nt][2 * h2 + 1]);
                *(float2*)(sP + row * 132 + kc * 32 + nt * 8 + 2 * t) = pv;
            }
        }
        __syncthreads();

        // ---- flash update of l and O scale ----
#pragma unroll
        for (int h2 = 0; h2 < 2; h2++) {
            int row = qq * 16 + h2 * 8 + g;
            float rsum = redS[row] + redS[64 + row] + redS[128 + row] + redS[192 + row];
            l_[h2] = l_[h2] * sc[h2] + rsum;
#pragma unroll
            for (int ct = 0; ct < 2; ct++) {
                o[ct][2 * h2] *= sc[h2];
                o[ct][2 * h2 + 1] *= sc[h2];
            }
        }

        // ---- PV: O += P(64x128) * V^T(128x64); warp = 16q x 16c ----
#pragma unroll 4
        for (int ks = 0; ks < 16; ks++) {
            const int fo = ks * 8;
            uint32_t ph[4], pl[4], vh[2][2], vl[2][2];
            const float* pr = sP + (qq * 16) * 132 + fo;
            split(pr[g * 132 + t],           ph[0], pl[0]);
            split(pr[(g + 8) * 132 + t],     ph[1], pl[1]);
            split(pr[g * 132 + t + 4],       ph[2], pl[2]);
            split(pr[(g + 8) * 132 + t + 4], ph[3], pl[3]);
#pragma unroll
            for (int ct = 0; ct < 2; ct++) {
                const float* vr = sV + (kc * 16 + ct * 8 + g) * 132 + fo;
                split(vr[t],     vh[ct][0], vl[ct][0]);
                split(vr[t + 4], vh[ct][1], vl[ct][1]);
            }
#pragma unroll
            for (int ct = 0; ct < 2; ct++)
                mma8(o[ct], ph[0], ph[1], ph[2], ph[3], vh[ct][0], vh[ct][1]);
#pragma unroll
            for (int ct = 0; ct < 2; ct++)
                mma8(o[ct], pl[0], pl[1], pl[2], pl[3], vh[ct][0], vh[ct][1]);
#pragma unroll
            for (int ct = 0; ct < 2; ct++)
                mma8(o[ct], ph[0], ph[1], ph[2], ph[3], vl[ct][0], vl[ct][1]);
        }
        __syncthreads();  // sP/sV reuse safe next kt
    }

    // ---- epilogue: normalize, write out[c][p] ----
#pragma unroll
    for (int h2 = 0; h2 < 2; h2++) {
        int pg = p0 + qq * 16 + h2 * 8 + g;
        float inv = 1.f / l_[h2];
#pragma unroll
        for (int ct = 0; ct < 2; ct++)
#pragma unroll
            for (int j = 0; j < 2; j++) {
                int c = kc * 16 + ct * 8 + 2 * t + j;
                out[c * 9216 + pg] = o[ct][2 * h2 + j] * inv;
            }
    }
}

// ---------------- launch ----------------
extern "C" void kernel_launch(void* const* d_in, const int* in_sizes, int n_in,
                              void* d_out, int out_size) {
    const float* X       = (const float*)d_in[0];
    const float* WQ_task = (const float*)d_in[1];
    const float* BQ_task = (const float*)d_in[2];
    const float* WK_task = (const float*)d_in[3];
    // d_in[4]=BK_task, d_in[11]=BK: row-constant in logits -> cancel in softmax
    const float* WV_task = (const float*)d_in[5];
    const float* BV_task = (const float*)d_in[6];
    const float* WQ_tm1  = (const float*)d_in[7];
    const float* WQ_x    = (const float*)d_in[8];
    const float* BQ      = (const float*)d_in[9];
    const float* WK_x    = (const float*)d_in[10];
    const float* prevQ   = (const float*)d_in[12];
    const float* Vconv_w = (const float*)d_in[13];
    const float* Vconv_b = (const float*)d_in[14];
    float* out = (float*)d_out;

    coef_kernel<<<1, 256>>>(WQ_task, BQ_task, WK_task, WQ_tm1, WQ_x, BQ, WK_x);
    qprep_kernel<<<dim3(36, 256), 256>>>(X, prevQ);
    conv_kernel<<<dim3(96, 2), 256>>>(X, Vconv_w, Vconv_b, WV_task, BV_task);

    float* qt_ptr = nullptr, *xt_ptr = nullptr, *qp_ptr = nullptr;
    cudaGetSymbolAddress((void**)&qp_ptr, g_Qp);
    cudaGetSymbolAddress((void**)&qt_ptr, g_Qt);
    cudaGetSymbolAddress((void**)&xt_ptr, g_Xt);
    trans_kernel<<<dim3(288, 8), dim3(32, 8)>>>(qp_ptr, qt_ptr);
    trans_kernel<<<dim3(288, 8), dim3(32, 8)>>>(X, xt_ptr);

    cudaFuncSetAttribute(attn_kernel, cudaFuncAttributeMaxDynamicSharedMemorySize, ATTN_SMEM);
    attn_kernel<<<144, 512, ATTN_SMEM>>>(out);
}

// round 13
// speedup vs baseline: 1.0026x; 1.0026x over previous
#include <cuda_runtime.h>
#include <cstdint>

// ---------------- scratch ----------------
__device__ float g_Qp[256 * 9216];   // Q'[f][p]
__device__ float g_Qt[9216 * 256];   // Q'[p][f]
__device__ float g_Xt[9216 * 256];   // X [p][f]
__device__ float g_Vt[64 * 9216];    // V [c][p]
__device__ float g_cA[8 * 256], g_cB[256], g_cC[256];

// ---------------- helpers ----------------
__device__ __forceinline__ float tf32hi(float x) {
    uint32_t u;
    asm("cvt.rna.tf32.f32 %0, %1;" : "=r"(u) : "f"(x));
    return __uint_as_float(u);
}
__device__ __forceinline__ void split(float v, uint32_t& hi, uint32_t& lo) {
    float h = tf32hi(v);
    hi = __float_as_uint(h);
    lo = __float_as_uint(v - h);
}
// D(16x8,f32) += A(16x8,tf32,row) * B(8x8,tf32,col)
__device__ __forceinline__ void mma8(float* d, uint32_t a0, uint32_t a1,
                                     uint32_t a2, uint32_t a3,
                                     uint32_t b0, uint32_t b1) {
    asm volatile(
        "mma.sync.aligned.m16n8k8.row.col.f32.tf32.tf32.f32 "
        "{%0,%1,%2,%3}, {%4,%5,%6,%7}, {%8,%9}, {%0,%1,%2,%3};"
        : "+f"(d[0]), "+f"(d[1]), "+f"(d[2]), "+f"(d[3])
        : "r"(a0), "r"(a1), "r"(a2), "r"(a3), "r"(b0), "r"(b1));
}

// ---------------- kernel 1: per-feature coefficients ----------------
__global__ void coef_kernel(const float* __restrict__ WQ_task, const float* __restrict__ BQ_task,
                            const float* __restrict__ WK_task, const float* __restrict__ WQ_tm1,
                            const float* __restrict__ WQ_x, const float* __restrict__ BQ,
                            const float* __restrict__ WK_x) {
    int f = threadIdx.x;
    float kA = WK_task[f] * WK_x[f];
    float sW = 0.f, sB = 0.f;
#pragma unroll
    for (int h = 0; h < 8; h++) {
        float wq = WQ_task[h * 256 + f];
        sW += wq;
        sB += wq * BQ[h * 256 + f] + BQ_task[h * 256 + f];
        g_cA[h * 256 + f] = kA * wq * WQ_tm1[h * 256 + f];
    }
    g_cB[f] = kA * WQ_x[f] * sW;
    g_cC[f] = kA * sB;
}

// ---------------- kernel 2: Q' [f][p] ----------------
__global__ void qprep_kernel(const float* __restrict__ X, const float* __restrict__ prevQ) {
    int f = blockIdx.y;
    int p = blockIdx.x * 256 + threadIdx.x;
    float q = fmaf(g_cB[f], X[f * 9216 + p], g_cC[f]);
#pragma unroll
    for (int h = 0; h < 8; h++)
        q = fmaf(g_cA[h * 256 + f], prevQ[(h * 256 + f) * 9216 + p], q);
    g_Qp[f * 9216 + p] = q;
}

// ---------------- kernel 3: transpose [f][p] -> [p][f] ----------------
__global__ void trans_kernel(const float* __restrict__ src, float* __restrict__ dst) {
    __shared__ float t[32][33];
    int bx = blockIdx.x, by = blockIdx.y;
    int tx = threadIdx.x, ty = threadIdx.y;
#pragma unroll
    for (int j = 0; j < 4; j++)
        t[ty + j * 8][tx] = src[(by * 32 + ty + j * 8) * 9216 + bx * 32 + tx];
    __syncthreads();
#pragma unroll
    for (int j = 0; j < 4; j++)
        dst[(bx * 32 + ty + j * 8) * 256 + by * 32 + tx] = t[tx][ty + j * 8];
}

// ---------------- kernel 4: 3x3 conv (F=256->C=64) + affine -> g_Vt[c][p] ----------------
__global__ void __launch_bounds__(256) conv_kernel(const float* __restrict__ X,
                                                   const float* __restrict__ Wc,
                                                   const float* __restrict__ Bc,
                                                   const float* __restrict__ WV,
                                                   const float* __restrict__ BV) {
    __shared__ float sx[4 * 294];
    __shared__ float sw[4 * 288];
    const int tid = threadIdx.x;
    const int w = blockIdx.x;
    const int cbase = blockIdx.y * 32;
    const int cl = tid >> 3;
    const int c = cbase + cl;
    const int h0 = (tid & 7) * 12;
    float acc[12];
#pragma unroll
    for (int i = 0; i < 12; i++) acc[i] = 0.f;
    for (int fc = 0; fc < 256; fc += 4) {
        __syncthreads();
        for (int i = tid; i < 4 * 294; i += 256) {
            int ff = i / 294, r = i % 294;
            int dw = r / 98, hh = r % 98;
            int ww = w + dw - 1;
            float v = 0.f;
            if (ww >= 0 && ww < 96 && hh >= 1 && hh <= 96)
                v = X[(fc + ff) * 9216 + ww * 96 + hh - 1];
            sx[i] = v;
        }
        for (int i = tid; i < 4 * 288; i += 256) {
            int ff = i / 288, r = i % 288;
            sw[i] = Wc[((cbase + r / 9) * 256 + fc + ff) * 9 + r % 9];
        }
        __syncthreads();
#pragma unroll
        for (int ff = 0; ff < 4; ff++) {
            float wv[9];
#pragma unroll
            for (int s = 0; s < 9; s++) wv[s] = sw[ff * 288 + cl * 9 + s];
#pragma unroll
            for (int dw = 0; dw < 3; dw++) {
                float xr[14];
#pragma unroll
                for (int j = 0; j < 14; j++) xr[j] = sx[ff * 294 + dw * 98 + h0 + j];
#pragma unroll
                for (int hi = 0; hi < 12; hi++)
#pragma unroll
                    for (int dh = 0; dh < 3; dh++)
                        acc[hi] = fmaf(xr[hi + dh], wv[dw * 3 + dh], acc[hi]);
            }
        }
    }
    float wv_ = WV[c], bv_ = BV[c], bc_ = Bc[c];
#pragma unroll
    for (int hi = 0; hi < 12; hi++)
        g_Vt[c * 9216 + w * 96 + h0 + hi] = fmaf(wv_, acc[hi] + bc_, bv_);
}

// ---------------- kernel 5: flash attention via mma.sync tf32 ----------------
// grid 144: CTA = 64 queries x all 9216 keys (72 tiles of 128).
// 512 thr = 16 warps = 4 q-quarters(16q) x 4 k-cols(32k). 3-pass tf32 split.
// smem floats: sQ 64x260 | sX 2x(128x36) | sP 64x132 | sV 64x132 | redM/redS 4x64
static const int SQ = 0, SX0 = 16640, SX1 = 21248, SP = 25856, SV = 34304;
static const int RM = 42752, RS = 43008;
static const int ATTN_SMEM = 43264 * 4;

__device__ __forceinline__ void ldgX(int cc, int tid, float4* rv) {
    int q0 = (cc >> 3) << 7, fb = (cc & 7) << 5;
#pragma unroll
    for (int j = 0; j < 2; j++) {
        int idx = tid + j * 512;
        int key = idx >> 3, f4 = idx & 7;
        rv[j] = *(const float4*)(g_Xt + (q0 + key) * 256 + fb + f4 * 4);
    }
}
__device__ __forceinline__ void stsX(float* dst, int tid, const float4* rv) {
#pragma unroll
    for (int j = 0; j < 2; j++) {
        int idx = tid + j * 512;
        int key = idx >> 3, f4 = idx & 7;
        *(float4*)(dst + key * 36 + f4 * 4) = rv[j];
    }
}

__global__ void __launch_bounds__(512, 1)
attn_kernel(float* __restrict__ out) {
    extern __shared__ float sm[];
    const int tid = threadIdx.x;
    const int w = tid >> 5, l = tid & 31;
    const int g = l >> 2, t = l & 3;
    const int qq = w >> 2;     // query quarter: rows qq*16..+15
    const int kc = w & 3;      // key column: keys kc*32..+31 / channels kc*16..+15
    const int p0 = blockIdx.x * 64;

    float* sQ = sm + SQ;
    float* sXb[2] = { sm + SX0, sm + SX1 };
    float* sP = sm + SP;
    float* sV = sm + SV;
    float* redM = sm + RM;
    float* redS = sm + RS;

    // stage Q tile [64][260]
#pragma unroll
    for (int i = 0; i < 8; i++) {
        int idx = tid + i * 512;
        int q = idx >> 6, f4 = idx & 63;
        *(float4*)(sQ + q * 260 + f4 * 4) = *(const float4*)(g_Qt + (p0 + q) * 256 + f4 * 4);
    }

    float4 rv[2];
    ldgX(0, tid, rv);
    __syncthreads();

    float o[2][4];
#pragma unroll
    for (int b = 0; b < 2; b++)
#pragma unroll
        for (int j = 0; j < 4; j++) o[b][j] = 0.f;
    float m_[2] = { -1e30f, -1e30f }, l_[2] = { 0.f, 0.f };

    for (int kt = 0; kt < 72; kt++) {
        const int q0 = kt * 128;
        float s[4][4];
#pragma unroll
        for (int n = 0; n < 4; n++)
#pragma unroll
            for (int j = 0; j < 4; j++) s[n][j] = 0.f;

        // ---- QK: 8 chunks of 32 features ----
        for (int ch = 0; ch < 8; ch++) {
            const int cc = kt * 8 + ch;
            float* sX = sXb[cc & 1];
            stsX(sX, tid, rv);
            if (cc + 1 < 576) ldgX(cc + 1, tid, rv);
            __syncthreads();

#pragma unroll
            for (int ks = 0; ks < 4; ks++) {
                const int fo = ch * 32 + ks * 8;
                uint32_t ah[4], al[4], bh[4][2], bl[4][2];
                const float* qr = sQ + (qq * 16) * 260 + fo;
                split(qr[g * 260 + t],           ah[0], al[0]);
                split(qr[(g + 8) * 260 + t],     ah[1], al[1]);
                split(qr[g * 260 + t + 4],       ah[2], al[2]);
                split(qr[(g + 8) * 260 + t + 4], ah[3], al[3]);
#pragma unroll
                for (int nt = 0; nt < 4; nt++) {
                    const float* xr = sX + (kc * 32 + nt * 8 + g) * 36 + ks * 8;
                    split(xr[t],     bh[nt][0], bl[nt][0]);
                    split(xr[t + 4], bh[nt][1], bl[nt][1]);
                }
#pragma unroll
                for (int nt = 0; nt < 4; nt++)
                    mma8(s[nt], ah[0], ah[1], ah[2], ah[3], bh[nt][0], bh[nt][1]);
#pragma unroll
                for (int nt = 0; nt < 4; nt++)
                    mma8(s[nt], al[0], al[1], al[2], al[3], bh[nt][0], bh[nt][1]);
#pragma unroll
                for (int nt = 0; nt < 4; nt++)
                    mma8(s[nt], ah[0], ah[1], ah[2], ah[3], bl[nt][0], bl[nt][1]);
            }
            __syncthreads();
        }

        // ---- softmax part 1: row maxes (rows qq*16 + h2*8 + g) ----
        float rm[2];
#pragma unroll
        for (int h2 = 0; h2 < 2; h2++) {
            float v = s[0][2 * h2];
#pragma unroll
            for (int nt = 0; nt < 4; nt++) {
                v = fmaxf(v, s[nt][2 * h2]);
                v = fmaxf(v, s[nt][2 * h2 + 1]);
            }
            v = fmaxf(v, __shfl_xor_sync(0xffffffffu, v, 1));
            v = fmaxf(v, __shfl_xor_sync(0xffffffffu, v, 2));
            rm[h2] = v;
        }
        if (t == 0) {
#pragma unroll
            for (int h2 = 0; h2 < 2; h2++)
                redM[kc * 64 + qq * 16 + h2 * 8 + g] = rm[h2];
        }
        __syncthreads();

        // ---- stage V tile [64c][128k] (LDG early, hides under exp) ----
#pragma unroll
        for (int j = 0; j < 4; j++) {
            int idx = tid + j * 512;
            int c = idx >> 5, k4 = idx & 31;
            float4 v = *(const float4*)(g_Vt + c * 9216 + q0 + k4 * 4);
            *(float4*)(sV + c * 132 + k4 * 4) = v;
        }

        // ---- softmax part 2: exp, sums, P to smem ----
        float mn[2], sc[2];
#pragma unroll
        for (int h2 = 0; h2 < 2; h2++) {
            int row = qq * 16 + h2 * 8 + g;
            float mx = fmaxf(fmaxf(redM[row], redM[64 + row]),
                             fmaxf(redM[128 + row], redM[192 + row]));
            mn[h2] = fmaxf(m_[h2], mx);
            sc[h2] = __expf(m_[h2] - mn[h2]);
            m_[h2] = mn[h2];
            float rs = 0.f;
#pragma unroll
            for (int nt = 0; nt < 4; nt++) {
                float e0 = __expf(s[nt][2 * h2] - mn[h2]);
                float e1 = __expf(s[nt][2 * h2 + 1] - mn[h2]);
                s[nt][2 * h2] = e0;
                s[nt][2 * h2 + 1] = e1;
                rs += e0 + e1;
            }
            rs += __shfl_xor_sync(0xffffffffu, rs, 1);
            rs += __shfl_xor_sync(0xffffffffu, rs, 2);
            if (t == 0) redS[kc * 64 + row] = rs;
        }
        // write P: [q][k]
#pragma unroll
        for (int h2 = 0; h2 < 2; h2++) {
            int row = qq * 16 + h2 * 8 + g;
#pragma unroll
            for (int nt = 0; nt < 4; nt++) {
                float2 pv = make_float2(s[nt][2 * h2], s[nt][2 * h2 + 1]);
                *(float2*)(sP + row * 132 + kc * 32 + nt * 8 + 2 * t) = pv;
            }
        }
        __syncthreads();

        // ---- flash update of l and O scale ----
#pragma unroll
        for (int h2 = 0; h2 < 2; h2++) {
            int row = qq * 16 + h2 * 8 + g;
            float rsum = redS[row] + redS[64 + row] + redS[128 + row] + redS[192 + row];
            l_[h2] = l_[h2] * sc[h2] + rsum;
#pragma unroll
            for (int ct = 0; ct < 2; ct++) {
                o[ct][2 * h2] *= sc[h2];
                o[ct][2 * h2 + 1] *= sc[h2];
            }
        }

        // ---- PV: O += P(64x128) * V^T(128x64); warp = 16q x 16c ----
#pragma unroll 4
        for (int ks = 0; ks < 16; ks++) {
            const int fo = ks * 8;
            uint32_t ph[4], pl[4], vh[2][2], vl[2][2];
            const float* pr = sP + (qq * 16) * 132 + fo;
            split(pr[g * 132 + t],           ph[0], pl[0]);
            split(pr[(g + 8) * 132 + t],     ph[1], pl[1]);
            split(pr[g * 132 + t + 4],       ph[2], pl[2]);
            split(pr[(g + 8) * 132 + t + 4], ph[3], pl[3]);
#pragma unroll
            for (int ct = 0; ct < 2; ct++) {
                const float* vr = sV + (kc * 16 + ct * 8 + g) * 132 + fo;
                split(vr[t],     vh[ct][0], vl[ct][0]);
                split(vr[t + 4], vh[ct][1], vl[ct][1]);
            }
#pragma unroll
            for (int ct = 0; ct < 2; ct++)
                mma8(o[ct], ph[0], ph[1], ph[2], ph[3], vh[ct][0], vh[ct][1]);
#pragma unroll
            for (int ct = 0; ct < 2; ct++)
                mma8(o[ct], pl[0], pl[1], pl[2], pl[3], vh[ct][0], vh[ct][1]);
#pragma unroll
            for (int ct = 0; ct < 2; ct++)
                mma8(o[ct], ph[0], ph[1], ph[2], ph[3], vl[ct][0], vl[ct][1]);
        }
        __syncthreads();  // sP/sV reuse safe next kt
    }

    // ---- epilogue: normalize, write out[c][p] ----
#pragma unroll
    for (int h2 = 0; h2 < 2; h2++) {
        int pg = p0 + qq * 16 + h2 * 8 + g;
        float inv = 1.f / l_[h2];
#pragma unroll
        for (int ct = 0; ct < 2; ct++)
#pragma unroll
            for (int j = 0; j < 2; j++) {
                int c = kc * 16 + ct * 8 + 2 * t + j;
                out[c * 9216 + pg] = o[ct][2 * h2 + j] * inv;
            }
    }
}

// ---------------- launch ----------------
extern "C" void kernel_launch(void* const* d_in, const int* in_sizes, int n_in,
                              void* d_out, int out_size) {
    const float* X       = (const float*)d_in[0];
    const float* WQ_task = (const float*)d_in[1];
    const float* BQ_task = (const float*)d_in[2];
    const float* WK_task = (const float*)d_in[3];
    // d_in[4]=BK_task, d_in[11]=BK: row-constant in logits -> cancel in softmax
    const float* WV_task = (const float*)d_in[5];
    const float* BV_task = (const float*)d_in[6];
    const float* WQ_tm1  = (const float*)d_in[7];
    const float* WQ_x    = (const float*)d_in[8];
    const float* BQ      = (const float*)d_in[9];
    const float* WK_x    = (const float*)d_in[10];
    const float* prevQ   = (const float*)d_in[12];
    const float* Vconv_w = (const float*)d_in[13];
    const float* Vconv_b = (const float*)d_in[14];
    float* out = (float*)d_out;

    coef_kernel<<<1, 256>>>(WQ_task, BQ_task, WK_task, WQ_tm1, WQ_x, BQ, WK_x);
    qprep_kernel<<<dim3(36, 256), 256>>>(X, prevQ);
    conv_kernel<<<dim3(96, 2), 256>>>(X, Vconv_w, Vconv_b, WV_task, BV_task);

    float* qt_ptr = nullptr, *xt_ptr = nullptr, *qp_ptr = nullptr;
    cudaGetSymbolAddress((void**)&qp_ptr, g_Qp);
    cudaGetSymbolAddress((void**)&qt_ptr, g_Qt);
    cudaGetSymbolAddress((void**)&xt_ptr, g_Xt);
    trans_kernel<<<dim3(288, 8), dim3(32, 8)>>>(qp_ptr, qt_ptr);
    trans_kernel<<<dim3(288, 8), dim3(32, 8)>>>(X, xt_ptr);

    cudaFuncSetAttribute(attn_kernel, cudaFuncAttributeMaxDynamicSharedMemorySize, ATTN_SMEM);
    attn_kernel<<<144, 512, ATTN_SMEM>>>(out);
}

// round 14
// speedup vs baseline: 1.0047x; 1.0021x over previous
#include <cuda_runtime.h>
#include <cstdint>

// ---------------- scratch ----------------
__device__ float g_Qp[256 * 9216];   // Q'[f][p]
__device__ float g_Qt[9216 * 256];   // Q'[p][f]
__device__ float g_Xt[9216 * 256];   // X [p][f]
__device__ float g_Vt[64 * 9216];    // V [c][p]
__device__ float g_cA[8 * 256], g_cB[256], g_cC[256];

// ---------------- helpers ----------------
__device__ __forceinline__ float tf32hi(float x) {
    uint32_t u;
    asm("cvt.rna.tf32.f32 %0, %1;" : "=r"(u) : "f"(x));
    return __uint_as_float(u);
}
__device__ __forceinline__ void split(float v, uint32_t& hi, uint32_t& lo) {
    float h = tf32hi(v);
    hi = __float_as_uint(h);
    lo = __float_as_uint(v - h);
}
// D(16x8,f32) += A(16x8,tf32,row) * B(8x8,tf32,col)
__device__ __forceinline__ void mma8(float* d, uint32_t a0, uint32_t a1,
                                     uint32_t a2, uint32_t a3,
                                     uint32_t b0, uint32_t b1) {
    asm volatile(
        "mma.sync.aligned.m16n8k8.row.col.f32.tf32.tf32.f32 "
        "{%0,%1,%2,%3}, {%4,%5,%6,%7}, {%8,%9}, {%0,%1,%2,%3};"
        : "+f"(d[0]), "+f"(d[1]), "+f"(d[2]), "+f"(d[3])
        : "r"(a0), "r"(a1), "r"(a2), "r"(a3), "r"(b0), "r"(b1));
}

// ---------------- kernel 1: per-feature coefficients ----------------
__global__ void coef_kernel(const float* __restrict__ WQ_task, const float* __restrict__ BQ_task,
                            const float* __restrict__ WK_task, const float* __restrict__ WQ_tm1,
                            const float* __restrict__ WQ_x, const float* __restrict__ BQ,
                            const float* __restrict__ WK_x) {
    int f = threadIdx.x;
    float kA = WK_task[f] * WK_x[f];
    float sW = 0.f, sB = 0.f;
#pragma unroll
    for (int h = 0; h < 8; h++) {
        float wq = WQ_task[h * 256 + f];
        sW += wq;
        sB += wq * BQ[h * 256 + f] + BQ_task[h * 256 + f];
        g_cA[h * 256 + f] = kA * wq * WQ_tm1[h * 256 + f];
    }
    g_cB[f] = kA * WQ_x[f] * sW;
    g_cC[f] = kA * sB;
}

// ---------------- kernel 2: Q' [f][p] ----------------
__global__ void qprep_kernel(const float* __restrict__ X, const float* __restrict__ prevQ) {
    int f = blockIdx.y;
    int p = blockIdx.x * 256 + threadIdx.x;
    float q = fmaf(g_cB[f], X[f * 9216 + p], g_cC[f]);
#pragma unroll
    for (int h = 0; h < 8; h++)
        q = fmaf(g_cA[h * 256 + f], prevQ[(h * 256 + f) * 9216 + p], q);
    g_Qp[f * 9216 + p] = q;
}

// ---------------- kernel 3: transpose [f][p] -> [p][f] ----------------
__global__ void trans_kernel(const float* __restrict__ src, float* __restrict__ dst) {
    __shared__ float t[32][33];
    int bx = blockIdx.x, by = blockIdx.y;
    int tx = threadIdx.x, ty = threadIdx.y;
#pragma unroll
    for (int j = 0; j < 4; j++)
        t[ty + j * 8][tx] = src[(by * 32 + ty + j * 8) * 9216 + bx * 32 + tx];
    __syncthreads();
#pragma unroll
    for (int j = 0; j < 4; j++)
        dst[(bx * 32 + ty + j * 8) * 256 + by * 32 + tx] = t[tx][ty + j * 8];
}

// ---------------- kernel 4: 3x3 conv (F=256->C=64) + affine -> g_Vt[c][p] ----------------
__global__ void __launch_bounds__(256) conv_kernel(const float* __restrict__ X,
                                                   const float* __restrict__ Wc,
                                                   const float* __restrict__ Bc,
                                                   const float* __restrict__ WV,
                                                   const float* __restrict__ BV) {
    __shared__ float sx[4 * 294];
    __shared__ float sw[4 * 288];
    const int tid = threadIdx.x;
    const int w = blockIdx.x;
    const int cbase = blockIdx.y * 32;
    const int cl = tid >> 3;
    const int c = cbase + cl;
    const int h0 = (tid & 7) * 12;
    float acc[12];
#pragma unroll
    for (int i = 0; i < 12; i++) acc[i] = 0.f;
    for (int fc = 0; fc < 256; fc += 4) {
        __syncthreads();
        for (int i = tid; i < 4 * 294; i += 256) {
            int ff = i / 294, r = i % 294;
            int dw = r / 98, hh = r % 98;
            int ww = w + dw - 1;
            float v = 0.f;
            if (ww >= 0 && ww < 96 && hh >= 1 && hh <= 96)
                v = X[(fc + ff) * 9216 + ww * 96 + hh - 1];
            sx[i] = v;
        }
        for (int i = tid; i < 4 * 288; i += 256) {
            int ff = i / 288, r = i % 288;
            sw[i] = Wc[((cbase + r / 9) * 256 + fc + ff) * 9 + r % 9];
        }
        __syncthreads();
#pragma unroll
        for (int ff = 0; ff < 4; ff++) {
            float wv[9];
#pragma unroll
            for (int s = 0; s < 9; s++) wv[s] = sw[ff * 288 + cl * 9 + s];
#pragma unroll
            for (int dw = 0; dw < 3; dw++) {
                float xr[14];
#pragma unroll
                for (int j = 0; j < 14; j++) xr[j] = sx[ff * 294 + dw * 98 + h0 + j];
#pragma unroll
                for (int hi = 0; hi < 12; hi++)
#pragma unroll
                    for (int dh = 0; dh < 3; dh++)
                        acc[hi] = fmaf(xr[hi + dh], wv[dw * 3 + dh], acc[hi]);
            }
        }
    }
    float wv_ = WV[c], bv_ = BV[c], bc_ = Bc[c];
#pragma unroll
    for (int hi = 0; hi < 12; hi++)
        g_Vt[c * 9216 + w * 96 + h0 + hi] = fmaf(wv_, acc[hi] + bc_, bv_);
}

// ---------------- kernel 5: flash attention via mma.sync tf32 ----------------
// grid 144: CTA = 64 queries x all 9216 keys (72 tiles of 128).
// 512 thr = 16 warps = 4 q-quarters(16q) x 4 k-cols(32k). 3-pass tf32 split.
// smem floats: sQ 64x260 | sX 2x(128x36) | sP 64x132 | sV 64x132 | redM/redS 4x64
static const int SQ = 0, SX0 = 16640, SX1 = 21248, SP = 25856, SV = 34304;
static const int RM = 42752, RS = 43008;
static const int ATTN_SMEM = 43264 * 4;

__device__ __forceinline__ void ldgX(int cc, int tid, float4* rv) {
    int q0 = (cc >> 3) << 7, fb = (cc & 7) << 5;
#pragma unroll
    for (int j = 0; j < 2; j++) {
        int idx = tid + j * 512;
        int key = idx >> 3, f4 = idx & 7;
        rv[j] = *(const float4*)(g_Xt + (q0 + key) * 256 + fb + f4 * 4);
    }
}
__device__ __forceinline__ void stsX(float* dst, int tid, const float4* rv) {
#pragma unroll
    for (int j = 0; j < 2; j++) {
        int idx = tid + j * 512;
        int key = idx >> 3, f4 = idx & 7;
        *(float4*)(dst + key * 36 + f4 * 4) = rv[j];
    }
}

__global__ void __launch_bounds__(512, 1)
attn_kernel(float* __restrict__ out) {
    extern __shared__ float sm[];
    const int tid = threadIdx.x;
    const int w = tid >> 5, l = tid & 31;
    const int g = l >> 2, t = l & 3;
    const int qq = w >> 2;     // query quarter: rows qq*16..+15
    const int kc = w & 3;      // key column: keys kc*32..+31 / channels kc*16..+15
    const int p0 = blockIdx.x * 64;

    float* sQ = sm + SQ;
    float* sXb[2] = { sm + SX0, sm + SX1 };
    float* sP = sm + SP;
    float* sV = sm + SV;
    float* redM = sm + RM;
    float* redS = sm + RS;

    // stage Q tile [64][260]
#pragma unroll
    for (int i = 0; i < 8; i++) {
        int idx = tid + i * 512;
        int q = idx >> 6, f4 = idx & 63;
        *(float4*)(sQ + q * 260 + f4 * 4) = *(const float4*)(g_Qt + (p0 + q) * 256 + f4 * 4);
    }

    float4 rv[2];
    ldgX(0, tid, rv);
    __syncthreads();

    float o[2][4];
#pragma unroll
    for (int b = 0; b < 2; b++)
#pragma unroll
        for (int j = 0; j < 4; j++) o[b][j] = 0.f;
    float m_[2] = { -1e30f, -1e30f }, l_[2] = { 0.f, 0.f };

    for (int kt = 0; kt < 72; kt++) {
        const int q0 = kt * 128;
        float s[4][4];
#pragma unroll
        for (int n = 0; n < 4; n++)
#pragma unroll
            for (int j = 0; j < 4; j++) s[n][j] = 0.f;

        // ---- QK: 8 chunks of 32 features ----
        for (int ch = 0; ch < 8; ch++) {
            const int cc = kt * 8 + ch;
            float* sX = sXb[cc & 1];
            stsX(sX, tid, rv);
            if (cc + 1 < 576) ldgX(cc + 1, tid, rv);
            __syncthreads();

#pragma unroll
            for (int ks = 0; ks < 4; ks++) {
                const int fo = ch * 32 + ks * 8;
                uint32_t ah[4], al[4], bh[4][2], bl[4][2];
                const float* qr = sQ + (qq * 16) * 260 + fo;
                split(qr[g * 260 + t],           ah[0], al[0]);
                split(qr[(g + 8) * 260 + t],     ah[1], al[1]);
                split(qr[g * 260 + t + 4],       ah[2], al[2]);
                split(qr[(g + 8) * 260 + t + 4], ah[3], al[3]);
#pragma unroll
                for (int nt = 0; nt < 4; nt++) {
                    const float* xr = sX + (kc * 32 + nt * 8 + g) * 36 + ks * 8;
                    split(xr[t],     bh[nt][0], bl[nt][0]);
                    split(xr[t + 4], bh[nt][1], bl[nt][1]);
                }
#pragma unroll
                for (int nt = 0; nt < 4; nt++)
                    mma8(s[nt], ah[0], ah[1], ah[2], ah[3], bh[nt][0], bh[nt][1]);
#pragma unroll
                for (int nt = 0; nt < 4; nt++)
                    mma8(s[nt], al[0], al[1], al[2], al[3], bh[nt][0], bh[nt][1]);
#pragma unroll
                for (int nt = 0; nt < 4; nt++)
                    mma8(s[nt], ah[0], ah[1], ah[2], ah[3], bl[nt][0], bl[nt][1]);
            }
            __syncthreads();
        }

        // ---- softmax part 1: row maxes (rows qq*16 + h2*8 + g) ----
        float rm[2];
#pragma unroll
        for (int h2 = 0; h2 < 2; h2++) {
            float v = s[0][2 * h2];
#pragma unroll
            for (int nt = 0; nt < 4; nt++) {
                v = fmaxf(v, s[nt][2 * h2]);
                v = fmaxf(v, s[nt][2 * h2 + 1]);
            }
            v = fmaxf(v, __shfl_xor_sync(0xffffffffu, v, 1));
            v = fmaxf(v, __shfl_xor_sync(0xffffffffu, v, 2));
            rm[h2] = v;
        }
        if (t == 0) {
#pragma unroll
            for (int h2 = 0; h2 < 2; h2++)
                redM[kc * 64 + qq * 16 + h2 * 8 + g] = rm[h2];
        }
        __syncthreads();

        // ---- stage V tile [64c][128k] (LDG early, hides under exp) ----
#pragma unroll
        for (int j = 0; j < 4; j++) {
            int idx = tid + j * 512;
            int c = idx >> 5, k4 = idx & 31;
            float4 v = *(const float4*)(g_Vt + c * 9216 + q0 + k4 * 4);
            *(float4*)(sV + c * 132 + k4 * 4) = v;
        }

        // ---- softmax part 2: exp, sums, P to smem ----
        float mn[2], sc[2];
#pragma unroll
        for (int h2 = 0; h2 < 2; h2++) {
            int row = qq * 16 + h2 * 8 + g;
            float mx = fmaxf(fmaxf(redM[row], redM[64 + row]),
                             fmaxf(redM[128 + row], redM[192 + row]));
            mn[h2] = fmaxf(m_[h2], mx);
            sc[h2] = __expf(m_[h2] - mn[h2]);
            m_[h2] = mn[h2];
            float rs = 0.f;
#pragma unroll
            for (int nt = 0; nt < 4; nt++) {
                float e0 = __expf(s[nt][2 * h2] - mn[h2]);
                float e1 = __expf(s[nt][2 * h2 + 1] - mn[h2]);
                s[nt][2 * h2] = e0;
                s[nt][2 * h2 + 1] = e1;
                rs += e0 + e1;
            }
            rs += __shfl_xor_sync(0xffffffffu, rs, 1);
            rs += __shfl_xor_sync(0xffffffffu, rs, 2);
            if (t == 0) redS[kc * 64 + row] = rs;
        }
        // write P: [q][k]
#pragma unroll
        for (int h2 = 0; h2 < 2; h2++) {
            int row = qq * 16 + h2 * 8 + g;
#pragma unroll
            for (int nt = 0; nt < 4; nt++) {
                float2 pv = make_float2(s[nt][2 * h2], s[nt][2 * h2 + 1]);
                *(float2*)(sP + row * 132 + kc * 32 + nt * 8 + 2 * t) = pv;
            }
        }
        __syncthreads();

        // ---- flash update of l and O scale ----
#pragma unroll
        for (int h2 = 0; h2 < 2; h2++) {
            int row = qq * 16 + h2 * 8 + g;
            float rsum = redS[row] + redS[64 + row] + redS[128 + row] + redS[192 + row];
            l_[h2] = l_[h2] * sc[h2] + rsum;
#pragma unroll
            for (int ct = 0; ct < 2; ct++) {
                o[ct][2 * h2] *= sc[h2];
                o[ct][2 * h2 + 1] *= sc[h2];
            }
        }

        // ---- PV: O += P(64x128) * V^T(128x64); warp = 16q x 16c ----
#pragma unroll 4
        for (int ks = 0; ks < 16; ks++) {
            const int fo = ks * 8;
            uint32_t ph[4], pl[4], vh[2][2], vl[2][2];
            const float* pr = sP + (qq * 16) * 132 + fo;
            split(pr[g * 132 + t],           ph[0], pl[0]);
            split(pr[(g + 8) * 132 + t],     ph[1], pl[1]);
            split(pr[g * 132 + t + 4],       ph[2], pl[2]);
            split(pr[(g + 8) * 132 + t + 4], ph[3], pl[3]);
#pragma unroll
            for (int ct = 0; ct < 2; ct++) {
                const float* vr = sV + (kc * 16 + ct * 8 + g) * 132 + fo;
                split(vr[t],     vh[ct][0], vl[ct][0]);
                split(vr[t + 4], vh[ct][1], vl[ct][1]);
            }
#pragma unroll
            for (int ct = 0; ct < 2; ct++)
                mma8(o[ct], ph[0], ph[1], ph[2], ph[3], vh[ct][0], vh[ct][1]);
#pragma unroll
            for (int ct = 0; ct < 2; ct++)
                mma8(o[ct], pl[0], pl[1], pl[2], pl[3], vh[ct][0], vh[ct][1]);
#pragma unroll
            for (int ct = 0; ct < 2; ct++)
                mma8(o[ct], ph[0], ph[1], ph[2], ph[3], vl[ct][0], vl[ct][1]);
        }
        __syncthreads();  // sP/sV reuse safe next kt
    }

    // ---- epilogue: normalize, write out[c][p] ----
#pragma unroll
    for (int h2 = 0; h2 < 2; h2++) {
        int pg = p0 + qq * 16 + h2 * 8 + g;
        float inv = 1.f / l_[h2];
#pragma unroll
        for (int ct = 0; ct < 2; ct++)
#pragma unroll
            for (int j = 0; j < 2; j++) {
                int c = kc * 16 + ct * 8 + 2 * t + j;
                out[c * 9216 + pg] = o[ct][2 * h2 + j] * inv;
            }
    }
}

// ---------------- launch ----------------
extern "C" void kernel_launch(void* const* d_in, const int* in_sizes, int n_in,
                              void* d_out, int out_size) {
    const float* X       = (const float*)d_in[0];
    const float* WQ_task = (const float*)d_in[1];
    const float* BQ_task = (const float*)d_in[2];
    const float* WK_task = (const float*)d_in[3];
    // d_in[4]=BK_task, d_in[11]=BK: row-constant in logits -> cancel in softmax
    const float* WV_task = (const float*)d_in[5];
    const float* BV_task = (const float*)d_in[6];
    const float* WQ_tm1  = (const float*)d_in[7];
    const float* WQ_x    = (const float*)d_in[8];
    const float* BQ      = (const float*)d_in[9];
    const float* WK_x    = (const float*)d_in[10];
    const float* prevQ   = (const float*)d_in[12];
    const float* Vconv_w = (const float*)d_in[13];
    const float* Vconv_b = (const float*)d_in[14];
    float* out = (float*)d_out;

    coef_kernel<<<1, 256>>>(WQ_task, BQ_task, WK_task, WQ_tm1, WQ_x, BQ, WK_x);
    qprep_kernel<<<dim3(36, 256), 256>>>(X, prevQ);
    conv_kernel<<<dim3(96, 2), 256>>>(X, Vconv_w, Vconv_b, WV_task, BV_task);

    float* qt_ptr = nullptr, *xt_ptr = nullptr, *qp_ptr = nullptr;
    cudaGetSymbolAddress((void**)&qp_ptr, g_Qp);
    cudaGetSymbolAddress((void**)&qt_ptr, g_Qt);
    cudaGetSymbolAddress((void**)&xt_ptr, g_Xt);
    trans_kernel<<<dim3(288, 8), dim3(32, 8)>>>(qp_ptr, qt_ptr);
    trans_kernel<<<dim3(288, 8), dim3(32, 8)>>>(X, xt_ptr);

    cudaFuncSetAttribute(attn_kernel, cudaFuncAttributeMaxDynamicSharedMemorySize, ATTN_SMEM);
    attn_kernel<<<144, 512, ATTN_SMEM>>>(out);
}

// round 15
// speedup vs baseline: 1.6651x; 1.6574x over previous
#include <cuda_runtime.h>
#include <cuda_fp16.h>
#include <cstdint>

// ---------------- scratch ----------------
__device__ float  g_Qp[256 * 9216];            // Q'[f][p] fp32
__device__ __half g_Q1[9216 * 256], g_Q2[9216 * 256];  // Q' [p][f] fp16 split
__device__ __half g_X1[9216 * 256], g_X2[9216 * 256];  // X  [p][f] fp16 split
__device__ __half g_V1[64 * 9216],  g_V2[64 * 9216];   // V  [c][p] fp16 split
__device__ float g_cA[8 * 256], g_cB[256], g_cC[256];

// D(16x8,f32) += A(16x16,f16,row) * B(16x8,f16,col)
__device__ __forceinline__ void mma16(float* d, uint32_t a0, uint32_t a1,
                                      uint32_t a2, uint32_t a3,
                                      uint32_t b0, uint32_t b1) {
    asm volatile(
        "mma.sync.aligned.m16n8k16.row.col.f32.f16.f16.f32 "
        "{%0,%1,%2,%3}, {%4,%5,%6,%7}, {%8,%9}, {%0,%1,%2,%3};"
        : "+f"(d[0]), "+f"(d[1]), "+f"(d[2]), "+f"(d[3])
        : "r"(a0), "r"(a1), "r"(a2), "r"(a3), "r"(b0), "r"(b1));
}
__device__ __forceinline__ uint32_t ldh2(const __half* p) {
    return *reinterpret_cast<const uint32_t*>(p);
}

// ---------------- kernel 1: per-feature coefficients ----------------
__global__ void coef_kernel(const float* __restrict__ WQ_task, const float* __restrict__ BQ_task,
                            const float* __restrict__ WK_task, const float* __restrict__ WQ_tm1,
                            const float* __restrict__ WQ_x, const float* __restrict__ BQ,
                            const float* __restrict__ WK_x) {
    int f = threadIdx.x;
    float kA = WK_task[f] * WK_x[f];
    float sW = 0.f, sB = 0.f;
#pragma unroll
    for (int h = 0; h < 8; h++) {
        float wq = WQ_task[h * 256 + f];
        sW += wq;
        sB += wq * BQ[h * 256 + f] + BQ_task[h * 256 + f];
        g_cA[h * 256 + f] = kA * wq * WQ_tm1[h * 256 + f];
    }
    g_cB[f] = kA * WQ_x[f] * sW;
    g_cC[f] = kA * sB;
}

// ---------------- kernel 2: Q' [f][p] fp32 ----------------
__global__ void qprep_kernel(const float* __restrict__ X, const float* __restrict__ prevQ) {
    int f = blockIdx.y;
    int p = blockIdx.x * 256 + threadIdx.x;
    float q = fmaf(g_cB[f], X[f * 9216 + p], g_cC[f]);
#pragma unroll
    for (int h = 0; h < 8; h++)
        q = fmaf(g_cA[h * 256 + f], prevQ[(h * 256 + f) * 9216 + p], q);
    g_Qp[f * 9216 + p] = q;
}

// ---------------- kernel 3: transpose [f][p] -> fp16 split [p][f] ----------------
__global__ void tsplit_kernel(const float* __restrict__ src,
                              __half* __restrict__ d1, __half* __restrict__ d2) {
    __shared__ float t[32][33];
    int bx = blockIdx.x, by = blockIdx.y;
    int tx = threadIdx.x, ty = threadIdx.y;
#pragma unroll
    for (int j = 0; j < 4; j++)
        t[ty + j * 8][tx] = src[(by * 32 + ty + j * 8) * 9216 + bx * 32 + tx];
    __syncthreads();
#pragma unroll
    for (int j = 0; j < 4; j++) {
        float v = t[tx][ty + j * 8];
        __half h1 = __float2half_rn(v);
        __half h2 = __float2half_rn(v - __half2float(h1));
        int p = bx * 32 + ty + j * 8, f = by * 32 + tx;
        d1[p * 256 + f] = h1;
        d2[p * 256 + f] = h2;
    }
}

// ---------------- kernel 4: 3x3 conv + affine -> fp16 split V[c][p] ----------------
__global__ void __launch_bounds__(256) conv_kernel(const float* __restrict__ X,
                                                   const float* __restrict__ Wc,
                                                   const float* __restrict__ Bc,
                                                   const float* __restrict__ WV,
                                                   const float* __restrict__ BV) {
    __shared__ float sx[4 * 294];
    __shared__ float sw[4 * 288];
    const int tid = threadIdx.x;
    const int w = blockIdx.x;
    const int cbase = blockIdx.y * 32;
    const int cl = tid >> 3;
    const int c = cbase + cl;
    const int h0 = (tid & 7) * 12;
    float acc[12];
#pragma unroll
    for (int i = 0; i < 12; i++) acc[i] = 0.f;
    for (int fc = 0; fc < 256; fc += 4) {
        __syncthreads();
        for (int i = tid; i < 4 * 294; i += 256) {
            int ff = i / 294, r = i % 294;
            int dw = r / 98, hh = r % 98;
            int ww = w + dw - 1;
            float v = 0.f;
            if (ww >= 0 && ww < 96 && hh >= 1 && hh <= 96)
                v = X[(fc + ff) * 9216 + ww * 96 + hh - 1];
            sx[i] = v;
        }
        for (int i = tid; i < 4 * 288; i += 256) {
            int ff = i / 288, r = i % 288;
            sw[i] = Wc[((cbase + r / 9) * 256 + fc + ff) * 9 + r % 9];
        }
        __syncthreads();
#pragma unroll
        for (int ff = 0; ff < 4; ff++) {
            float wv[9];
#pragma unroll
            for (int s = 0; s < 9; s++) wv[s] = sw[ff * 288 + cl * 9 + s];
#pragma unroll
            for (int dw = 0; dw < 3; dw++) {
                float xr[14];
#pragma unroll
                for (int j = 0; j < 14; j++) xr[j] = sx[ff * 294 + dw * 98 + h0 + j];
#pragma unroll
                for (int hi = 0; hi < 12; hi++)
#pragma unroll
                    for (int dh = 0; dh < 3; dh++)
                        acc[hi] = fmaf(xr[hi + dh], wv[dw * 3 + dh], acc[hi]);
            }
        }
    }
    float wv_ = WV[c], bv_ = BV[c], bc_ = Bc[c];
#pragma unroll
    for (int hi = 0; hi < 12; hi++) {
        float v = fmaf(wv_, acc[hi] + bc_, bv_);
        __half h1 = __float2half_rn(v);
        g_V1[c * 9216 + w * 96 + h0 + hi] = h1;
        g_V2[c * 9216 + w * 96 + h0 + hi] = __float2half_rn(v - __half2float(h1));
    }
}

// ---------------- kernel 5: flash attention, fp16 2-split mma.sync ----------------
// grid 144: CTA = 64 queries x 9216 keys (72 tiles of 128).
// 256 thr = 8 warps = 2 qh(32q) x 4 kc(32k). QK 3 passes, PV 2 passes.
// half-offsets in smem:
static const int QS = 264, XS = 40, PS = 136, VS = 136;
static const int SQ1 = 0, SQ2 = 16896, SX = 33792, SP = 54272, SV1 = 62976, SV2 = 71680;
static const int ATTN_SMEM = 80384 * 2 + 512 * 4;  // 162816 B

__device__ __forceinline__ void ldgX(int cc, int tid, uint4* rv) {
    int q0 = (cc >> 3) << 7, fb = (cc & 7) << 5;
#pragma unroll
    for (int j = 0; j < 2; j++) {
        int idx = tid + j * 256;
        int key = idx >> 2, u = idx & 3;
        rv[j]     = *(const uint4*)(g_X1 + (q0 + key) * 256 + fb + u * 8);
        rv[2 + j] = *(const uint4*)(g_X2 + (q0 + key) * 256 + fb + u * 8);
    }
}
__device__ __forceinline__ void stsX(__half* x1, __half* x2, int tid, const uint4* rv) {
#pragma unroll
    for (int j = 0; j < 2; j++) {
        int idx = tid + j * 256;
        int key = idx >> 2, u = idx & 3;
        *(uint4*)(x1 + key * XS + u * 8) = rv[j];
        *(uint4*)(x2 + key * XS + u * 8) = rv[2 + j];
    }
}

__global__ void __launch_bounds__(256, 1)
attn_kernel(float* __restrict__ out) {
    extern __shared__ __half smh[];
    const int tid = threadIdx.x;
    const int w = tid >> 5, l = tid & 31;
    const int g = l >> 2, t = l & 3;
    const int qh = w >> 2, kc = w & 3;
    const int p0 = blockIdx.x * 64;

    __half* sQ1 = smh + SQ1;
    __half* sQ2 = smh + SQ2;
    __half* sP = smh + SP;
    __half* sV1 = smh + SV1;
    __half* sV2 = smh + SV2;
    float* redM = (float*)(smh + 80384);
    float* redS = redM + 256;

    // stage Q splits [64][QS]
#pragma unroll
    for (int i = 0; i < 8; i++) {
        int idx = tid + i * 256;
        int q = idx >> 5, u = idx & 31;
        *(uint4*)(sQ1 + q * QS + u * 8) = *(const uint4*)(g_Q1 + (p0 + q) * 256 + u * 8);
        *(uint4*)(sQ2 + q * QS + u * 8) = *(const uint4*)(g_Q2 + (p0 + q) * 256 + u * 8);
    }

    uint4 rv[4];
    ldgX(0, tid, rv);
    __syncthreads();

    float o[2][2][4];
#pragma unroll
    for (int a = 0; a < 2; a++)
#pragma unroll
        for (int b = 0; b < 2; b++)
#pragma unroll
            for (int j = 0; j < 4; j++) o[a][b][j] = 0.f;
    float m_[2][2], l_[2][2];
#pragma unroll
    for (int a = 0; a < 2; a++)
#pragma unroll
        for (int b = 0; b < 2; b++) { m_[a][b] = -1e30f; l_[a][b] = 0.f; }

    for (int kt = 0; kt < 72; kt++) {
        const int q0 = kt * 128;
        float s[2][4][4];
#pragma unroll
        for (int a = 0; a < 2; a++)
#pragma unroll
            for (int n = 0; n < 4; n++)
#pragma unroll
                for (int j = 0; j < 4; j++) s[a][n][j] = 0.f;

        // ---- QK: 8 chunks of 32 features, fp16 3-pass ----
        for (int ch = 0; ch < 8; ch++) {
            const int cc = kt * 8 + ch;
            __half* x1 = smh + SX + (cc & 1) * 10240;
            __half* x2 = x1 + 5120;
            stsX(x1, x2, tid, rv);
            if (cc + 1 < 576) ldgX(cc + 1, tid, rv);
            __syncthreads();

#pragma unroll
            for (int ks = 0; ks < 2; ks++) {
                const int fo = ch * 32 + ks * 16;
                const int xo = ks * 16;
                uint32_t A1[2][4], A2[2][4], B1[4][2], B2[4][2];
#pragma unroll
                for (int qt = 0; qt < 2; qt++) {
                    const __half* q1 = sQ1 + (qh * 32 + qt * 16) * QS + fo;
                    const __half* q2 = sQ2 + (qh * 32 + qt * 16) * QS + fo;
                    A1[qt][0] = ldh2(q1 + g * QS + 2 * t);
                    A1[qt][1] = ldh2(q1 + (g + 8) * QS + 2 * t);
                    A1[qt][2] = ldh2(q1 + g * QS + 2 * t + 8);
                    A1[qt][3] = ldh2(q1 + (g + 8) * QS + 2 * t + 8);
                    A2[qt][0] = ldh2(q2 + g * QS + 2 * t);
                    A2[qt][1] = ldh2(q2 + (g + 8) * QS + 2 * t);
                    A2[qt][2] = ldh2(q2 + g * QS + 2 * t + 8);
                    A2[qt][3] = ldh2(q2 + (g + 8) * QS + 2 * t + 8);
                }
#pragma unroll
                for (int nt = 0; nt < 4; nt++) {
                    const __half* xr1 = x1 + (kc * 32 + nt * 8 + g) * XS + xo;
                    const __half* xr2 = x2 + (kc * 32 + nt * 8 + g) * XS + xo;
                    B1[nt][0] = ldh2(xr1 + 2 * t);
                    B1[nt][1] = ldh2(xr1 + 2 * t + 8);
                    B2[nt][0] = ldh2(xr2 + 2 * t);
                    B2[nt][1] = ldh2(xr2 + 2 * t + 8);
                }
#pragma unroll
                for (int qt = 0; qt < 2; qt++)
#pragma unroll
                    for (int nt = 0; nt < 4; nt++)
                        mma16(s[qt][nt], A1[qt][0], A1[qt][1], A1[qt][2], A1[qt][3],
                              B1[nt][0], B1[nt][1]);
#pragma unroll
                for (int qt = 0; qt < 2; qt++)
#pragma unroll
                    for (int nt = 0; nt < 4; nt++)
                        mma16(s[qt][nt], A2[qt][0], A2[qt][1], A2[qt][2], A2[qt][3],
                              B1[nt][0], B1[nt][1]);
#pragma unroll
                for (int qt = 0; qt < 2; qt++)
#pragma unroll
                    for (int nt = 0; nt < 4; nt++)
                        mma16(s[qt][nt], A1[qt][0], A1[qt][1], A1[qt][2], A1[qt][3],
                              B2[nt][0], B2[nt][1]);
            }
            __syncthreads();
        }

        // ---- softmax part 1: row maxes ----
        float rm[2][2];
#pragma unroll
        for (int qt = 0; qt < 2; qt++)
#pragma unroll
            for (int h2 = 0; h2 < 2; h2++) {
                float v = s[qt][0][2 * h2];
#pragma unroll
                for (int nt = 0; nt < 4; nt++) {
                    v = fmaxf(v, s[qt][nt][2 * h2]);
                    v = fmaxf(v, s[qt][nt][2 * h2 + 1]);
                }
                v = fmaxf(v, __shfl_xor_sync(0xffffffffu, v, 1));
                v = fmaxf(v, __shfl_xor_sync(0xffffffffu, v, 2));
                rm[qt][h2] = v;
            }
        if (t == 0) {
#pragma unroll
            for (int qt = 0; qt < 2; qt++)
#pragma unroll
                for (int h2 = 0; h2 < 2; h2++)
                    redM[kc * 64 + qh * 32 + qt * 16 + h2 * 8 + g] = rm[qt][h2];
        }
        __syncthreads();

        // ---- stage V splits [64c][128k] (LDG early, hides under exp) ----
#pragma unroll
        for (int j = 0; j < 4; j++) {
            int idx = tid + j * 256;
            int c = idx >> 4, u = idx & 15;
            *(uint4*)(sV1 + c * VS + u * 8) = *(const uint4*)(g_V1 + c * 9216 + q0 + u * 8);
            *(uint4*)(sV2 + c * VS + u * 8) = *(const uint4*)(g_V2 + c * 9216 + q0 + u * 8);
        }

        // ---- softmax part 2: exp, sums, P (fp16) to smem ----
        float mn[2][2], sc[2][2];
#pragma unroll
        for (int qt = 0; qt < 2; qt++)
#pragma unroll
            for (int h2 = 0; h2 < 2; h2++) {
                int row = qh * 32 + qt * 16 + h2 * 8 + g;
                float mx = fmaxf(fmaxf(redM[row], redM[64 + row]),
                                 fmaxf(redM[128 + row], redM[192 + row]));
                mn[qt][h2] = fmaxf(m_[qt][h2], mx);
                sc[qt][h2] = __expf(m_[qt][h2] - mn[qt][h2]);
                m_[qt][h2] = mn[qt][h2];
                float rs = 0.f;
#pragma unroll
                for (int nt = 0; nt < 4; nt++) {
                    float e0 = __expf(s[qt][nt][2 * h2] - mn[qt][h2]);
                    float e1 = __expf(s[qt][nt][2 * h2 + 1] - mn[qt][h2]);
                    s[qt][nt][2 * h2] = e0;
                    s[qt][nt][2 * h2 + 1] = e1;
                    rs += e0 + e1;
                }
                rs += __shfl_xor_sync(0xffffffffu, rs, 1);
                rs += __shfl_xor_sync(0xffffffffu, rs, 2);
                if (t == 0) redS[kc * 64 + row] = rs;
            }
#pragma unroll
        for (int qt = 0; qt < 2; qt++)
#pragma unroll
            for (int h2 = 0; h2 < 2; h2++) {
                int row = qh * 32 + qt * 16 + h2 * 8 + g;
#pragma unroll
                for (int nt = 0; nt < 4; nt++) {
                    __half2 pv = __floats2half2_rn(s[qt][nt][2 * h2], s[qt][nt][2 * h2 + 1]);
                    *(__half2*)(sP + row * PS + kc * 32 + nt * 8 + 2 * t) = pv;
                }
            }
        __syncthreads();

        // ---- flash update of l and O scale ----
#pragma unroll
        for (int qt = 0; qt < 2; qt++)
#pragma unroll
            for (int h2 = 0; h2 < 2; h2++) {
                int row = qh * 32 + qt * 16 + h2 * 8 + g;
                float rsum = redS[row] + redS[64 + row] + redS[128 + row] + redS[192 + row];
                l_[qt][h2] = l_[qt][h2] * sc[qt][h2] + rsum;
#pragma unroll
                for (int ct = 0; ct < 2; ct++) {
                    o[qt][ct][2 * h2] *= sc[qt][h2];
                    o[qt][ct][2 * h2 + 1] *= sc[qt][h2];
                }
            }

        // ---- PV: O += P(64x128) * V^T(128x64), fp16 2-pass; warp 32q x 16c ----
#pragma unroll 4
        for (int ks = 0; ks < 8; ks++) {
            const int fo = ks * 16;
            uint32_t PA[2][4], VB1[2][2], VB2[2][2];
#pragma unroll
            for (int qt = 0; qt < 2; qt++) {
                const __half* pr = sP + (qh * 32 + qt * 16) * PS + fo;
                PA[qt][0] = ldh2(pr + g * PS + 2 * t);
                PA[qt][1] = ldh2(pr + (g + 8) * PS + 2 * t);
                PA[qt][2] = ldh2(pr + g * PS + 2 * t + 8);
                PA[qt][3] = ldh2(pr + (g + 8) * PS + 2 * t + 8);
            }
#pragma unroll
            for (int ct = 0; ct < 2; ct++) {
                const __half* v1 = sV1 + (kc * 16 + ct * 8 + g) * VS + fo;
                const __half* v2 = sV2 + (kc * 16 + ct * 8 + g) * VS + fo;
                VB1[ct][0] = ldh2(v1 + 2 * t);
                VB1[ct][1] = ldh2(v1 + 2 * t + 8);
                VB2[ct][0] = ldh2(v2 + 2 * t);
                VB2[ct][1] = ldh2(v2 + 2 * t + 8);
            }
#pragma unroll
            for (int qt = 0; qt < 2; qt++)
#pragma unroll
                for (int ct = 0; ct < 2; ct++)
                    mma16(o[qt][ct], PA[qt][0], PA[qt][1], PA[qt][2], PA[qt][3],
                          VB1[ct][0], VB1[ct][1]);
#pragma unroll
            for (int qt = 0; qt < 2; qt++)
#pragma unroll
                for (int ct = 0; ct < 2; ct++)
                    mma16(o[qt][ct], PA[qt][0], PA[qt][1], PA[qt][2], PA[qt][3],
                          VB2[ct][0], VB2[ct][1]);
        }
        __syncthreads();  // sP/sV reuse safe next kt
    }

    // ---- epilogue: normalize, write out[c][p] ----
#pragma unroll
    for (int qt = 0; qt < 2; qt++)
#pragma unroll
        for (int h2 = 0; h2 < 2; h2++) {
            int pg = p0 + qh * 32 + qt * 16 + h2 * 8 + g;
            float inv = 1.f / l_[qt][h2];
#pragma unroll
            for (int ct = 0; ct < 2; ct++)
#pragma unroll
                for (int j = 0; j < 2; j++) {
                    int c = kc * 16 + ct * 8 + 2 * t + j;
                    out[c * 9216 + pg] = o[qt][ct][2 * h2 + j] * inv;
                }
        }
}

// ---------------- launch ----------------
extern "C" void kernel_launch(void* const* d_in, const int* in_sizes, int n_in,
                              void* d_out, int out_size) {
    const float* X       = (const float*)d_in[0];
    const float* WQ_task = (const float*)d_in[1];
    const float* BQ_task = (const float*)d_in[2];
    const float* WK_task = (const float*)d_in[3];
    // d_in[4]=BK_task, d_in[11]=BK: row-constant in logits -> cancel in softmax
    const float* WV_task = (const float*)d_in[5];
    const float* BV_task = (const float*)d_in[6];
    const float* WQ_tm1  = (const float*)d_in[7];
    const float* WQ_x    = (const float*)d_in[8];
    const float* BQ      = (const float*)d_in[9];
    const float* WK_x    = (const float*)d_in[10];
    const float* prevQ   = (const float*)d_in[12];
    const float* Vconv_w = (const float*)d_in[13];
    const float* Vconv_b = (const float*)d_in[14];
    float* out = (float*)d_out;

    coef_kernel<<<1, 256>>>(WQ_task, BQ_task, WK_task, WQ_tm1, WQ_x, BQ, WK_x);
    qprep_kernel<<<dim3(36, 256), 256>>>(X, prevQ);
    conv_kernel<<<dim3(96, 2), 256>>>(X, Vconv_w, Vconv_b, WV_task, BV_task);

    float* qp = nullptr;
    __half *q1, *q2, *x1, *x2;
    cudaGetSymbolAddress((void**)&qp, g_Qp);
    cudaGetSymbolAddress((void**)&q1, g_Q1);
    cudaGetSymbolAddress((void**)&q2, g_Q2);
    cudaGetSymbolAddress((void**)&x1, g_X1);
    cudaGetSymbolAddress((void**)&x2, g_X2);
    tsplit_kernel<<<dim3(288, 8), dim3(32, 8)>>>(qp, q1, q2);
    tsplit_kernel<<<dim3(288, 8), dim3(32, 8)>>>(X, x1, x2);

    cudaFuncSetAttribute(attn_kernel, cudaFuncAttributeMaxDynamicSharedMemorySize, ATTN_SMEM);
    attn_kernel<<<144, 256, ATTN_SMEM>>>(out);
}